// round 11
// baseline (speedup 1.0000x reference)
#include <cuda_runtime.h>
#include <cuda_bf16.h>
#include <cstdint>

// ---------------- problem constants ----------------
#define BATCH   4
#define LSEQ    2048
#define NROWS   (BATCH*LSEQ)        // 8192
#define DIM     512
#define D_INNER 1024
#define D_STATE 16
#define D_CONV  4
#define DT_RANK 32
#define XDBL    (DT_RANK + 2*D_STATE)  // 64
#define D_GEOM  256
#define EPSV    1e-5f
#define CS      16                   // scan chunks
#define TCH     (LSEQ/CS)            // 128 steps per chunk

#define W_IP (2*D_INNER*DIM)
#define W_XP (XDBL*D_INNER)
#define W_DT (D_INNER*DT_RANK)
#define W_MO (DIM*D_INNER)
#define W_MA (DIM*DIM)
#define W_GE (D_GEOM*DIM)

// ---------------- scratch (device globals; no allocation) ----------------
__device__ float g_hln  [NROWS * DIM];            // permuted k-layout
__device__ float g_xz   [NROWS * 2 * D_INNER];
__device__ float g_xconv[NROWS * D_INNER];        // permuted + rounded
__device__ float g_uT   [BATCH * D_INNER * LSEQ];
__device__ float g_dT   [BATCH * D_INNER * LSEQ];
__device__ float g_xdbl [NROWS * XDBL];           // cols<32 permuted
__device__ float g_yscan[NROWS * D_INNER];        // permuted + rounded
__device__ float g_hout [NROWS * DIM];            // permuted + rounded
__device__ float g_match[NROWS * DIM];
__device__ float g_geom [NROWS * D_GEOM];
__device__ float g_hchk [BATCH * D_INNER * CS * D_STATE];
__device__ float g_schk [BATCH * D_INNER * CS];
__device__ float g_h0   [BATCH * D_INNER * CS * D_STATE];
__device__ float g_wip[W_IP];   // all weights: permuted + rounded
__device__ float g_wxp[W_XP];
__device__ float g_wdt[W_DT];
__device__ float g_wmo[W_MO];
__device__ float g_wma[W_MA];
__device__ float g_wge[W_GE];

__device__ __forceinline__ uint32_t f2tf(float f) {
    uint32_t r; asm("cvt.rna.tf32.f32 %0, %1;" : "=r"(r) : "f"(f)); return r;
}
__device__ __forceinline__ float f2tf_f(float f) {
    return __uint_as_float(f2tf(f));
}
__device__ __forceinline__ float softplusf(float v) {
    return (v > 20.f) ? v : log1pf(__expf(v));
}
// k-permutation within 8-blocks: position(k) = 2*(k%4) + (k/4)%2
__device__ __forceinline__ int permc(int c) {
    return (c & ~7) | (((c & 3) << 1) | ((c >> 2) & 1));
}

__device__ __forceinline__ void cp16(uint32_t daddr, const void* gptr) {
    asm volatile("cp.async.cg.shared.global [%0], [%1], 16;" :: "r"(daddr), "l"(gptr));
}
__device__ __forceinline__ void cp_commit() {
    asm volatile("cp.async.commit_group;");
}
template<int N>
__device__ __forceinline__ void cp_wait() {
    asm volatile("cp.async.wait_group %0;" :: "n"(N));
}

__device__ __forceinline__ void mma_tf32(float* c, const uint32_t* a,
                                         uint32_t b0, uint32_t b1) {
    asm volatile(
        "mma.sync.aligned.m16n8k8.row.col.f32.tf32.tf32.f32 "
        "{%0,%1,%2,%3}, {%4,%5,%6,%7}, {%8,%9}, {%0,%1,%2,%3};"
        : "+f"(c[0]), "+f"(c[1]), "+f"(c[2]), "+f"(c[3])
        : "r"(a[0]), "r"(a[1]), "r"(a[2]), "r"(a[3]), "r"(b0), "r"(b1));
}

// ---------------- weight pre-rounding + permutation (split in two) ---------
__global__ void round_wip_kernel(const float* __restrict__ ip)
{
    int i = blockIdx.x * blockDim.x + threadIdx.x;
    if (i >= W_IP) return;
    int r = i / DIM, k = i % DIM;
    g_wip[r * DIM + permc(k)] = f2tf_f(ip[i]);
}
__global__ void round_wrest_kernel(const float* __restrict__ xp,
                                   const float* __restrict__ dt,
                                   const float* __restrict__ mo,
                                   const float* __restrict__ ma,
                                   const float* __restrict__ ge)
{
    int i = blockIdx.x * blockDim.x + threadIdx.x;
    int total = W_XP + W_DT + W_MO + W_MA + W_GE;
    if (i >= total) return;
    if (i < W_XP) { int r = i / D_INNER, k = i % D_INNER;
        g_wxp[r * D_INNER + permc(k)] = f2tf_f(xp[i]); return; }
    i -= W_XP;
    if (i < W_DT) { int r = i / DT_RANK, k = i % DT_RANK;
        g_wdt[r * DT_RANK + permc(k)] = f2tf_f(dt[i]); return; }
    i -= W_DT;
    if (i < W_MO) { int r = i / D_INNER, k = i % D_INNER;
        g_wmo[r * D_INNER + permc(k)] = f2tf_f(mo[i]); return; }
    i -= W_MO;
    if (i < W_MA) { int r = i / DIM, k = i % DIM;
        g_wma[r * DIM + permc(k)] = f2tf_f(ma[i]); return; }
    i -= W_MA;
    { int r = i / DIM, k = i % DIM;
      g_wge[r * DIM + permc(k)] = f2tf_f(ge[i]); }
}

// ---------------- layernorm ----------------
template<bool RNDPERM>
__global__ void layernorm_kernel(const float* __restrict__ in,
                                 const float* __restrict__ w,
                                 const float* __restrict__ b,
                                 float* __restrict__ out, int cols)
{
    int row = blockIdx.x;
    const float* p = in + (size_t)row * cols;
    float s = 0.f, sq = 0.f;
    for (int c = threadIdx.x; c < cols; c += blockDim.x) {
        float v = p[c]; s += v; sq += v * v;
    }
    int lane = threadIdx.x & 31, wid = threadIdx.x >> 5;
    #pragma unroll
    for (int o = 16; o; o >>= 1) {
        s  += __shfl_xor_sync(0xffffffffu, s,  o);
        sq += __shfl_xor_sync(0xffffffffu, sq, o);
    }
    __shared__ float shs[8], shq[8];
    if (!lane) { shs[wid] = s; shq[wid] = sq; }
    __syncthreads();
    if (threadIdx.x == 0) {
        float ts = 0.f, tq = 0.f;
        int nw = (blockDim.x + 31) >> 5;
        for (int i = 0; i < nw; i++) { ts += shs[i]; tq += shq[i]; }
        float mu  = ts / cols;
        float var = tq / cols - mu * mu;
        shs[0] = mu;
        shq[0] = rsqrtf(var + EPSV);
    }
    __syncthreads();
    float mu = shs[0], inv = shq[0];
    float* o = out + (size_t)row * cols;
    for (int c = threadIdx.x; c < cols; c += blockDim.x) {
        float v = (p[c] - mu) * inv * w[c] + b[c];
        if (RNDPERM) o[permc(c)] = f2tf_f(v);
        else         o[c] = v;
    }
}

// ---------------- tf32 mma.sync GEMM, cp.async 3-stage, 128xBN tile ----------
// BN=64: 3 CTAs/SM, warp tile 32x32. BN=128: 2 CTAs/SM, warp tile 32x64
// (doubled B-fragment reuse: 24 LDS.64 per 32 MMA).
#define EPI_NONE      0
#define EPI_RESID     2
#define EPI_BIAS      3
#define EPI_SOFTPL_T  4
#define EPI_RND       5

#define GBM 128
#define GBK 16
#define GLD 24
#define GST 3
#define GEMM_SMEM(BN) (GST * (GBM + (BN)) * GLD * 4)

template<int BN, int EPI, int KSPLIT, bool CVTA, bool PERMC>
__global__ __launch_bounds__(256, (BN == 64) ? 3 : 2)
void tgemm_kernel(const float* __restrict__ A, int lda,
                  const float* __restrict__ B,
                  const float* __restrict__ bias,
                  const float* __restrict__ resid,
                  float* __restrict__ C,
                  int M, int N, int K)
{
    const int WN = BN / 16;       // n8-fragments per warp
    extern __shared__ float smem[];
    float* ASbase = smem;
    float* BSbase = smem + GST * GBM * GLD;

    const int tid  = threadIdx.x;
    const int wid  = tid >> 5;
    const int lane = tid & 31;
    const int gid  = lane >> 2;
    const int tig  = lane & 3;
    const int wm   = (wid & 3) * 32;
    const int wn   = (wid >> 2) * (BN / 2);
    const int bm   = blockIdx.y * GBM;
    const int bn   = blockIdx.x * BN;

    const int kchunk = K / KSPLIT;
    const int kbeg   = (KSPLIT > 1) ? blockIdx.z * kchunk : 0;
    const int nslab  = kchunk / GBK;

    const float* Ag = A + (size_t)bm * lda + kbeg;
    const float* Bg = B + (size_t)bn * K + kbeg;

    const uint32_t sA = (uint32_t)__cvta_generic_to_shared(ASbase);
    const uint32_t sB = (uint32_t)__cvta_generic_to_shared(BSbase);

    auto issue = [&](int stage, int slab) {
        int k0 = slab * GBK;
        #pragma unroll
        for (int i = 0; i < 2; i++) {
            int id = tid + i * 256;
            int r = id >> 2, c = (id & 3) << 2;
            cp16(sA + (uint32_t)((stage * GBM + r) * GLD + c) * 4,
                 Ag + (size_t)r * lda + k0 + c);
        }
        #pragma unroll
        for (int i = 0; i < BN / 64; i++) {
            int id = tid + i * 256;
            int r = id >> 2, c = (id & 3) << 2;
            cp16(sB + (uint32_t)((stage * BN + r) * GLD + c) * 4,
                 Bg + (size_t)r * K + k0 + c);
        }
    };

    float acc[2][WN][4];
    #pragma unroll
    for (int i = 0; i < 2; i++)
        #pragma unroll
        for (int f = 0; f < WN; f++)
            #pragma unroll
            for (int j = 0; j < 4; j++)
                acc[i][f][j] = 0.f;

    #pragma unroll
    for (int s = 0; s < GST - 1; s++) {
        if (s < nslab) issue(s, s);
        cp_commit();
    }

    for (int i = 0; i < nslab; i++) {
        if (i + GST - 1 < nslab) cp_wait<GST - 2>(); else cp_wait<0>();
        __syncthreads();
        if (i + GST - 1 < nslab) issue((i + GST - 1) % GST, i + GST - 1);
        cp_commit();

        const float* AS = ASbase + (i % GST) * GBM * GLD;
        const float* BS = BSbase + (i % GST) * BN * GLD;
        #pragma unroll
        for (int kk = 0; kk < GBK; kk += 8) {
            uint32_t af[2][4];
            #pragma unroll
            for (int t2 = 0; t2 < 2; t2++) {
                int rbase = wm + t2 * 16;
                float2 aA = *reinterpret_cast<const float2*>(
                    &AS[(rbase + gid) * GLD + kk + 2 * tig]);
                float2 aB = *reinterpret_cast<const float2*>(
                    &AS[(rbase + 8 + gid) * GLD + kk + 2 * tig]);
                if (CVTA) {
                    af[t2][0] = f2tf(aA.x); af[t2][1] = f2tf(aB.x);
                    af[t2][2] = f2tf(aA.y); af[t2][3] = f2tf(aB.y);
                } else {
                    af[t2][0] = __float_as_uint(aA.x);
                    af[t2][1] = __float_as_uint(aB.x);
                    af[t2][2] = __float_as_uint(aA.y);
                    af[t2][3] = __float_as_uint(aB.y);
                }
            }
            #pragma unroll
            for (int f = 0; f < WN; f++) {
                float2 bb = *reinterpret_cast<const float2*>(
                    &BS[(wn + f * 8 + gid) * GLD + kk + 2 * tig]);
                uint32_t b0 = __float_as_uint(bb.x);
                uint32_t b1 = __float_as_uint(bb.y);
                mma_tf32(acc[0][f], af[0], b0, b1);
                mma_tf32(acc[1][f], af[1], b0, b1);
            }
        }
    }

    // ---- epilogue ----
    if (EPI == EPI_SOFTPL_T) {
        // stage tile in smem (pitch 129), then coalesced column stores
        __syncthreads();
        float* sD = smem;
        #pragma unroll
        for (int t2 = 0; t2 < 2; t2++) {
            #pragma unroll
            for (int rr = 0; rr < 2; rr++) {
                int row = wm + t2 * 16 + gid + rr * 8;
                #pragma unroll
                for (int f = 0; f < WN; f++) {
                    int cl = wn + f * 8 + 2 * tig;
                    sD[(cl)     * 129 + row] = acc[t2][f][rr * 2 + 0];
                    sD[(cl + 1) * 129 + row] = acc[t2][f][rr * 2 + 1];
                }
            }
        }
        __syncthreads();
        int bb2 = bm >> 11, t0 = bm & (LSEQ - 1);
        for (int e = tid; e < BN * 128; e += 256) {
            int cl = e >> 7, tt = e & 127;
            float v = softplusf(sD[cl * 129 + tt] + bias[bn + cl]);
            C[((size_t)(bb2 * D_INNER) + bn + cl) * LSEQ + t0 + tt] = v;
        }
        return;
    }

    #pragma unroll
    for (int t2 = 0; t2 < 2; t2++) {
        #pragma unroll
        for (int rr = 0; rr < 2; rr++) {
            int row = bm + wm + t2 * 16 + gid + rr * 8;
            float* crow = C + (size_t)row * N;
            const float* rrow = (EPI == EPI_RESID) ? (resid + (size_t)row * N) : nullptr;
            #pragma unroll
            for (int f = 0; f < WN; f++) {
                int col = bn + wn + f * 8 + 2 * tig;
                float v0 = acc[t2][f][rr * 2 + 0];
                float v1 = acc[t2][f][rr * 2 + 1];
                if (KSPLIT > 1) {
                    int c0 = col, c1 = col + 1;
                    if (PERMC) {
                        c0 = (c0 < DT_RANK) ? permc(c0) : c0;
                        c1 = (c1 < DT_RANK) ? permc(c1) : c1;
                    }
                    atomicAdd(&crow[c0], v0);
                    atomicAdd(&crow[c1], v1);
                } else if (EPI == EPI_RND) {
                    crow[PERMC ? permc(col)     : col]     = f2tf_f(v0);
                    crow[PERMC ? permc(col + 1) : col + 1] = f2tf_f(v1);
                } else {
                    if (EPI == EPI_RESID) {
                        v0 += bias[col]     + rrow[col];
                        v1 += bias[col + 1] + rrow[col + 1];
                    } else if (EPI == EPI_BIAS) {
                        v0 += bias[col]; v1 += bias[col + 1];
                    }
                    *reinterpret_cast<float2*>(&crow[col]) = make_float2(v0, v1);
                }
            }
        }
    }
}

// ---------------- depthwise causal conv + silu, dual-layout output ----------------
__global__ __launch_bounds__(256)
void conv_silu_T_kernel(const float* __restrict__ conv_w,
                        const float* __restrict__ conv_b)
{
    __shared__ float sx[35][33];
    __shared__ float so[32][33];
    int t0 = blockIdx.x * 32, d0 = blockIdx.y * 32, b = blockIdx.z;
    int tx = threadIdx.x, ty = threadIdx.y;

    for (int r = ty; r < 35; r += 8) {
        int t = t0 - 3 + r;
        float v = (t >= 0) ? g_xz[((size_t)(b * LSEQ) + t) * (2 * D_INNER) + d0 + tx] : 0.f;
        sx[r][tx] = v;
    }
    __syncthreads();

    int d = d0 + tx;
    int dp = permc(d);
    float w0 = conv_w[d * 4 + 0], w1 = conv_w[d * 4 + 1];
    float w2 = conv_w[d * 4 + 2], w3 = conv_w[d * 4 + 3];
    float bb = conv_b[d];
    for (int r = ty; r < 32; r += 8) {
        float acc = bb;
        acc = fmaf(w0, sx[r][tx],     acc);
        acc = fmaf(w1, sx[r + 1][tx], acc);
        acc = fmaf(w2, sx[r + 2][tx], acc);
        acc = fmaf(w3, sx[r + 3][tx], acc);
        float sv = acc / (1.f + __expf(-acc));
        g_xconv[((size_t)(b * LSEQ) + t0 + r) * D_INNER + dp] = f2tf_f(sv);
        so[tx][r] = sv;
    }
    __syncthreads();

    for (int r = ty; r < 32; r += 8)
        g_uT[((size_t)(b * D_INNER) + d0 + r) * LSEQ + t0 + tx] = so[r][tx];
}

// ---------------- chunked selective scan ----------------
__global__ __launch_bounds__(256)
void scan_pass1(const float* __restrict__ A_log)
{
    int c = blockIdx.x, db = blockIdx.y, b = blockIdx.z;
    int n = threadIdx.x & 15, ch = threadIdx.x >> 4;
    int d = db * 16 + ch;

    float Av = -__expf(A_log[d * D_STATE + n]);
    const float* dTp = g_dT + ((size_t)(b * D_INNER) + d) * LSEQ + c * TCH;
    const float* uTp = g_uT + ((size_t)(b * D_INNER) + d) * LSEQ + c * TCH;
    const float* xd  = g_xdbl + ((size_t)(b * LSEQ) + c * TCH) * XDBL;

    float h = 0.f, S = 0.f;
    #pragma unroll 2
    for (int j = 0; j < TCH; j += 4) {
        float4 dv = *reinterpret_cast<const float4*>(dTp + j);
        float4 uv = *reinterpret_cast<const float4*>(uTp + j);
        float dl[4] = {dv.x, dv.y, dv.z, dv.w};
        float uu[4] = {uv.x, uv.y, uv.z, uv.w};
        #pragma unroll
        for (int q = 0; q < 4; q++) {
            float Bv = xd[(size_t)(j + q) * XDBL + DT_RANK + n];
            float a  = __expf(dl[q] * Av);
            h = fmaf(a, h, dl[q] * uu[q] * Bv);
            S += dl[q];
        }
    }
    g_hchk[(((size_t)(b * D_INNER) + d) * CS + c) * D_STATE + n] = h;
    if (n == 0)
        g_schk[((size_t)(b * D_INNER) + d) * CS + c] = S;
}

__global__ void scan_combine(const float* __restrict__ A_log)
{
    int idx = blockIdx.x * blockDim.x + threadIdx.x;
    if (idx >= BATCH * D_INNER * D_STATE) return;
    int n = idx & 15;
    int d = (idx >> 4) & (D_INNER - 1);
    int b = idx >> 14;
    float Av = -__expf(A_log[d * D_STATE + n]);
    size_t base = ((size_t)(b * D_INNER) + d) * CS;
    float h0 = 0.f;
    #pragma unroll
    for (int c = 0; c < CS; c++) {
        g_h0[(base + c) * D_STATE + n] = h0;
        float S = g_schk[base + c];
        h0 = g_hchk[(base + c) * D_STATE + n] + __expf(Av * S) * h0;
    }
}

__global__ __launch_bounds__(256)
void scan_pass2(const float* __restrict__ A_log, const float* __restrict__ Dv)
{
    int c = blockIdx.x, db = blockIdx.y, b = blockIdx.z;
    int n = threadIdx.x & 15, ch = threadIdx.x >> 4;
    int d = db * 16 + ch;

    float Av = -__expf(A_log[d * D_STATE + n]);
    float Dd = Dv[d];

    const float* dTp = g_dT + ((size_t)(b * D_INNER) + d) * LSEQ + c * TCH;
    const float* uTp = g_uT + ((size_t)(b * D_INNER) + d) * LSEQ + c * TCH;
    const float* xd  = g_xdbl + ((size_t)(b * LSEQ) + c * TCH) * XDBL;
    const float* zP  = g_xz + ((size_t)(b * LSEQ) + c * TCH) * (2 * D_INNER) + D_INNER + d;
    float* yP = g_yscan + ((size_t)(b * LSEQ) + c * TCH) * D_INNER + permc(d);

    float h = g_h0[(((size_t)(b * D_INNER) + d) * CS + c) * D_STATE + n];

    #pragma unroll 2
    for (int j = 0; j < TCH; j += 4) {
        float4 dv = *reinterpret_cast<const float4*>(dTp + j);
        float4 uv = *reinterpret_cast<const float4*>(uTp + j);
        float dl[4] = {dv.x, dv.y, dv.z, dv.w};
        float uu[4] = {uv.x, uv.y, uv.z, uv.w};
        #pragma unroll
        for (int q = 0; q < 4; q++) {
            float Bv = xd[(size_t)(j + q) * XDBL + DT_RANK + n];
            float Cv = xd[(size_t)(j + q) * XDBL + DT_RANK + D_STATE + n];
            float a  = __expf(dl[q] * Av);
            h = fmaf(a, h, dl[q] * uu[q] * Bv);
            float p = h * Cv;
            #pragma unroll
            for (int o = 8; o; o >>= 1)
                p += __shfl_xor_sync(0xffffffffu, p, o);
            if (n == 0) {
                float z = zP[(size_t)(j + q) * (2 * D_INNER)];
                float sig = z / (1.f + __expf(-z));
                yP[(size_t)(j + q) * D_INNER] = f2tf_f((p + uu[q] * Dd) * sig);
            }
        }
    }
}

// ---------------- launch ----------------
static float* sym(const void* symbol) {
    void* p = nullptr;
    cudaGetSymbolAddress(&p, symbol);
    return (float*)p;
}

extern "C" void kernel_launch(void* const* d_in, const int* in_sizes, int n_in,
                              void* d_out, int out_size)
{
    const float* x         = (const float*)d_in[0];
    const float* norm_w    = (const float*)d_in[1];
    const float* norm_b    = (const float*)d_in[2];
    const float* in_proj_w = (const float*)d_in[3];
    const float* conv_w    = (const float*)d_in[4];
    const float* conv_b    = (const float*)d_in[5];
    const float* x_proj_w  = (const float*)d_in[6];
    const float* dt_proj_w = (const float*)d_in[7];
    const float* dt_proj_b = (const float*)d_in[8];
    const float* A_log     = (const float*)d_in[9];
    const float* Dv        = (const float*)d_in[10];
    const float* mix_out_w = (const float*)d_in[11];
    const float* match_w   = (const float*)d_in[12];
    const float* match_b   = (const float*)d_in[13];
    const float* geom_w    = (const float*)d_in[14];
    const float* geom_b    = (const float*)d_in[15];
    const float* normm_w   = (const float*)d_in[16];
    const float* normm_b   = (const float*)d_in[17];
    const float* normg_w   = (const float*)d_in[18];
    const float* normg_b   = (const float*)d_in[19];

    float* p_hln   = sym(g_hln);
    float* p_xdbl  = sym(g_xdbl);
    float* p_xz    = sym(g_xz);
    float* p_xconv = sym(g_xconv);
    float* p_dT    = sym(g_dT);
    float* p_yscan = sym(g_yscan);
    float* p_hout  = sym(g_hout);
    float* p_match = sym(g_match);
    float* p_geom  = sym(g_geom);
    float* p_wip   = sym(g_wip);
    float* p_wxp   = sym(g_wxp);
    float* p_wdt   = sym(g_wdt);
    float* p_wmo   = sym(g_wmo);
    float* p_wma   = sym(g_wma);
    float* p_wge   = sym(g_wge);

    float* out_match = (float*)d_out;
    float* out_geom  = (float*)d_out + (size_t)NROWS * DIM;

    // dynamic smem opt-in (idempotent)
    cudaFuncSetAttribute(tgemm_kernel<128, EPI_NONE, 1, false, false>,
                         cudaFuncAttributeMaxDynamicSharedMemorySize, GEMM_SMEM(128));
    cudaFuncSetAttribute(tgemm_kernel<64, EPI_NONE, 4, false, true>,
                         cudaFuncAttributeMaxDynamicSharedMemorySize, GEMM_SMEM(64));
    cudaFuncSetAttribute(tgemm_kernel<128, EPI_SOFTPL_T, 1, true, false>,
                         cudaFuncAttributeMaxDynamicSharedMemorySize, GEMM_SMEM(128));
    cudaFuncSetAttribute(tgemm_kernel<128, EPI_RND, 1, false, true>,
                         cudaFuncAttributeMaxDynamicSharedMemorySize, GEMM_SMEM(128));
    cudaFuncSetAttribute(tgemm_kernel<128, EPI_RESID, 1, false, false>,
                         cudaFuncAttributeMaxDynamicSharedMemorySize, GEMM_SMEM(128));
    cudaFuncSetAttribute(tgemm_kernel<128, EPI_BIAS, 1, false, false>,
                         cudaFuncAttributeMaxDynamicSharedMemorySize, GEMM_SMEM(128));

    // kernel order: #4 = in_proj (profiled by ncu next round)
    {
        int total = W_XP + W_DT + W_MO + W_MA + W_GE;
        round_wrest_kernel<<<(total + 255) / 256, 256>>>(x_proj_w, dt_proj_w,
                                                         mix_out_w, match_w, geom_w);
    }
    layernorm_kernel<true><<<NROWS, 256>>>(x, norm_w, norm_b, p_hln, DIM);
    round_wip_kernel<<<(W_IP + 255) / 256, 256>>>(in_proj_w);

    // 4. xz = h @ in_proj_w^T   [8192, 2048] K=512  (1024 CTAs, BN=128)
    {
        dim3 grid(2 * D_INNER / 128, NROWS / GBM);
        tgemm_kernel<128, EPI_NONE, 1, false, false><<<grid, 256, GEMM_SMEM(128)>>>(
            p_hln, DIM, p_wip, nullptr, nullptr, p_xz, NROWS, 2 * D_INNER, DIM);
    }

    // 5. u = silu(conv(xm))
    {
        dim3 grid(LSEQ / 32, D_INNER / 32, BATCH);
        conv_silu_T_kernel<<<grid, dim3(32, 8)>>>(conv_w, conv_b);
    }

    // 6. x_dbl = u @ x_proj_w^T [8192,64] K=1024, split-K=4 (BN=64)
    cudaMemsetAsync(p_xdbl, 0, (size_t)NROWS * XDBL * sizeof(float));
    {
        dim3 grid(1, NROWS / GBM, 4);
        tgemm_kernel<64, EPI_NONE, 4, false, true><<<grid, 256, GEMM_SMEM(64)>>>(
            p_xconv, D_INNER, p_wxp, nullptr, nullptr, p_xdbl, NROWS, XDBL, D_INNER);
    }

    // 7. deltaT = softplus(dt @ dt_proj_w^T + b), smem-transposed coalesced store
    {
        dim3 grid(D_INNER / 128, NROWS / GBM);
        tgemm_kernel<128, EPI_SOFTPL_T, 1, true, false><<<grid, 256, GEMM_SMEM(128)>>>(
            p_xdbl, XDBL, p_wdt, dt_proj_b, nullptr, p_dT, NROWS, D_INNER, DT_RANK);
    }

    // 8/9/10. chunked selective scan
    {
        dim3 grid(CS, D_INNER / 16, BATCH);
        scan_pass1<<<grid, 256>>>(A_log);
        scan_combine<<<(BATCH * D_INNER * D_STATE) / 256, 256>>>(A_log);
        scan_pass2<<<grid, 256>>>(A_log, Dv);
    }

    // 11. h_out = y @ mix_out_w^T (rounds+permutes in epilogue)
    {
        dim3 grid(DIM / 128, NROWS / GBM);
        tgemm_kernel<128, EPI_RND, 1, false, true><<<grid, 256, GEMM_SMEM(128)>>>(
            p_yscan, D_INNER, p_wmo, nullptr, nullptr, p_hout, NROWS, DIM, D_INNER);
    }

    // 12. match_pre = residual + h_out @ match_w^T + match_b
    {
        dim3 grid(DIM / 128, NROWS / GBM);
        tgemm_kernel<128, EPI_RESID, 1, false, false><<<grid, 256, GEMM_SMEM(128)>>>(
            p_hout, DIM, p_wma, match_b, x, p_match, NROWS, DIM, DIM);
    }

    // 13. geom_pre = h_out @ geom_w^T + geom_b
    {
        dim3 grid(D_GEOM / 128, NROWS / GBM);
        tgemm_kernel<128, EPI_BIAS, 1, false, false><<<grid, 256, GEMM_SMEM(128)>>>(
            p_hout, DIM, p_wge, geom_b, nullptr, p_geom, NROWS, D_GEOM, DIM);
    }

    // 14/15. final layernorms into d_out
    layernorm_kernel<false><<<NROWS, 256>>>(p_match, normm_w, normm_b, out_match, DIM);
    layernorm_kernel<false><<<NROWS, 256>>>(p_geom,  normg_w, normg_b, out_geom,  D_GEOM);
}

// round 12
// speedup vs baseline: 1.0965x; 1.0965x over previous
#include <cuda_runtime.h>
#include <cuda_bf16.h>
#include <cstdint>

// ---------------- problem constants ----------------
#define BATCH   4
#define LSEQ    2048
#define NROWS   (BATCH*LSEQ)        // 8192
#define DIM     512
#define D_INNER 1024
#define D_STATE 16
#define D_CONV  4
#define DT_RANK 32
#define XDBL    (DT_RANK + 2*D_STATE)  // 64
#define D_GEOM  256
#define EPSV    1e-5f
#define CS      16                   // scan chunks
#define TCH     (LSEQ/CS)            // 128 steps per chunk

#define W_IP (2*D_INNER*DIM)
#define W_XP (XDBL*D_INNER)
#define W_DT (D_INNER*DT_RANK)
#define W_MO (DIM*D_INNER)
#define W_MA (DIM*DIM)
#define W_GE (D_GEOM*DIM)

// ---------------- scratch (device globals; no allocation) ----------------
__device__ float g_hln  [NROWS * DIM];            // permuted k-layout
__device__ float g_xz   [NROWS * 2 * D_INNER];
__device__ float g_xconv[NROWS * D_INNER];        // permuted + rounded
__device__ float g_uT   [BATCH * D_INNER * LSEQ];
__device__ float g_dT   [BATCH * D_INNER * LSEQ];
__device__ float g_xdbl [NROWS * XDBL];           // cols<32 permuted
__device__ float g_yscan[NROWS * D_INNER];        // permuted + rounded
__device__ float g_hout [NROWS * DIM];            // permuted + rounded
__device__ float g_match[NROWS * DIM];
__device__ float g_geom [NROWS * D_GEOM];
__device__ float g_hchk [BATCH * D_INNER * CS * D_STATE];
__device__ float g_schk [BATCH * D_INNER * CS];
__device__ float g_h0   [BATCH * D_INNER * CS * D_STATE];
__device__ float g_wip[W_IP];   // all weights: permuted + rounded
__device__ float g_wxp[W_XP];
__device__ float g_wdt[W_DT];
__device__ float g_wmo[W_MO];
__device__ float g_wma[W_MA];
__device__ float g_wge[W_GE];

__device__ __forceinline__ uint32_t f2tf(float f) {
    uint32_t r; asm("cvt.rna.tf32.f32 %0, %1;" : "=r"(r) : "f"(f)); return r;
}
__device__ __forceinline__ float f2tf_f(float f) {
    return __uint_as_float(f2tf(f));
}
__device__ __forceinline__ float softplusf(float v) {
    return (v > 20.f) ? v : log1pf(__expf(v));
}
// k-permutation within 8-blocks: position(k) = 2*(k%4) + (k/4)%2
__device__ __forceinline__ int permc(int c) {
    return (c & ~7) | (((c & 3) << 1) | ((c >> 2) & 1));
}

__device__ __forceinline__ void cp16(uint32_t daddr, const void* gptr) {
    asm volatile("cp.async.cg.shared.global [%0], [%1], 16;" :: "r"(daddr), "l"(gptr));
}
__device__ __forceinline__ void cp_commit() {
    asm volatile("cp.async.commit_group;");
}
template<int N>
__device__ __forceinline__ void cp_wait() {
    asm volatile("cp.async.wait_group %0;" :: "n"(N));
}

__device__ __forceinline__ void mma_tf32(float* c, const uint32_t* a,
                                         uint32_t b0, uint32_t b1) {
    asm volatile(
        "mma.sync.aligned.m16n8k8.row.col.f32.tf32.tf32.f32 "
        "{%0,%1,%2,%3}, {%4,%5,%6,%7}, {%8,%9}, {%0,%1,%2,%3};"
        : "+f"(c[0]), "+f"(c[1]), "+f"(c[2]), "+f"(c[3])
        : "r"(a[0]), "r"(a[1]), "r"(a[2]), "r"(a[3]), "r"(b0), "r"(b1));
}

// ---------------- weight pre-rounding + permutation ----------------
__global__ void round_wip_kernel(const float* __restrict__ ip)
{
    int i = blockIdx.x * blockDim.x + threadIdx.x;
    if (i >= W_IP) return;
    int r = i / DIM, k = i % DIM;
    g_wip[r * DIM + permc(k)] = f2tf_f(ip[i]);
}
__global__ void round_wrest_kernel(const float* __restrict__ xp,
                                   const float* __restrict__ dt,
                                   const float* __restrict__ mo,
                                   const float* __restrict__ ma,
                                   const float* __restrict__ ge)
{
    int i = blockIdx.x * blockDim.x + threadIdx.x;
    int total = W_XP + W_DT + W_MO + W_MA + W_GE;
    if (i >= total) return;
    if (i < W_XP) { int r = i / D_INNER, k = i % D_INNER;
        g_wxp[r * D_INNER + permc(k)] = f2tf_f(xp[i]); return; }
    i -= W_XP;
    if (i < W_DT) { int r = i / DT_RANK, k = i % DT_RANK;
        g_wdt[r * DT_RANK + permc(k)] = f2tf_f(dt[i]); return; }
    i -= W_DT;
    if (i < W_MO) { int r = i / D_INNER, k = i % D_INNER;
        g_wmo[r * D_INNER + permc(k)] = f2tf_f(mo[i]); return; }
    i -= W_MO;
    if (i < W_MA) { int r = i / DIM, k = i % DIM;
        g_wma[r * DIM + permc(k)] = f2tf_f(ma[i]); return; }
    i -= W_MA;
    { int r = i / DIM, k = i % DIM;
      g_wge[r * DIM + permc(k)] = f2tf_f(ge[i]); }
}

// ---------------- layernorm ----------------
template<bool RNDPERM>
__global__ void layernorm_kernel(const float* __restrict__ in,
                                 const float* __restrict__ w,
                                 const float* __restrict__ b,
                                 float* __restrict__ out, int cols)
{
    int row = blockIdx.x;
    const float* p = in + (size_t)row * cols;
    float s = 0.f, sq = 0.f;
    for (int c = threadIdx.x; c < cols; c += blockDim.x) {
        float v = p[c]; s += v; sq += v * v;
    }
    int lane = threadIdx.x & 31, wid = threadIdx.x >> 5;
    #pragma unroll
    for (int o = 16; o; o >>= 1) {
        s  += __shfl_xor_sync(0xffffffffu, s,  o);
        sq += __shfl_xor_sync(0xffffffffu, sq, o);
    }
    __shared__ float shs[8], shq[8];
    if (!lane) { shs[wid] = s; shq[wid] = sq; }
    __syncthreads();
    if (threadIdx.x == 0) {
        float ts = 0.f, tq = 0.f;
        int nw = (blockDim.x + 31) >> 5;
        for (int i = 0; i < nw; i++) { ts += shs[i]; tq += shq[i]; }
        float mu  = ts / cols;
        float var = tq / cols - mu * mu;
        shs[0] = mu;
        shq[0] = rsqrtf(var + EPSV);
    }
    __syncthreads();
    float mu = shs[0], inv = shq[0];
    float* o = out + (size_t)row * cols;
    for (int c = threadIdx.x; c < cols; c += blockDim.x) {
        float v = (p[c] - mu) * inv * w[c] + b[c];
        if (RNDPERM) o[permc(c)] = f2tf_f(v);
        else         o[c] = v;
    }
}

// ---------------- tf32 mma.sync GEMM, cp.async 3-stage, 128xBN tile ----------
#define EPI_NONE      0
#define EPI_RESID     2
#define EPI_BIAS      3
#define EPI_SOFTPL_T  4
#define EPI_RND       5

#define GBM 128
#define GBK 16
#define GLD 24
#define GST 3
#define GEMM_SMEM(BN) (GST * (GBM + (BN)) * GLD * 4)

template<int BN, int EPI, int KSPLIT, bool CVTA, bool PERMC>
__global__ __launch_bounds__(256, (BN == 64) ? 3 : 2)
void tgemm_kernel(const float* __restrict__ A, int lda,
                  const float* __restrict__ B,
                  const float* __restrict__ bias,
                  const float* __restrict__ resid,
                  float* __restrict__ C,
                  int M, int N, int K)
{
    const int WN = BN / 16;
    extern __shared__ float smem[];
    float* ASbase = smem;
    float* BSbase = smem + GST * GBM * GLD;

    const int tid  = threadIdx.x;
    const int wid  = tid >> 5;
    const int lane = tid & 31;
    const int gid  = lane >> 2;
    const int tig  = lane & 3;
    const int wm   = (wid & 3) * 32;
    const int wn   = (wid >> 2) * (BN / 2);
    const int bm   = blockIdx.y * GBM;
    const int bn   = blockIdx.x * BN;

    const int kchunk = K / KSPLIT;
    const int kbeg   = (KSPLIT > 1) ? blockIdx.z * kchunk : 0;
    const int nslab  = kchunk / GBK;

    const float* Ag = A + (size_t)bm * lda + kbeg;
    const float* Bg = B + (size_t)bn * K + kbeg;

    const uint32_t sA = (uint32_t)__cvta_generic_to_shared(ASbase);
    const uint32_t sB = (uint32_t)__cvta_generic_to_shared(BSbase);

    auto issue = [&](int stage, int slab) {
        int k0 = slab * GBK;
        #pragma unroll
        for (int i = 0; i < 2; i++) {
            int id = tid + i * 256;
            int r = id >> 2, c = (id & 3) << 2;
            cp16(sA + (uint32_t)((stage * GBM + r) * GLD + c) * 4,
                 Ag + (size_t)r * lda + k0 + c);
        }
        #pragma unroll
        for (int i = 0; i < BN / 64; i++) {
            int id = tid + i * 256;
            int r = id >> 2, c = (id & 3) << 2;
            cp16(sB + (uint32_t)((stage * BN + r) * GLD + c) * 4,
                 Bg + (size_t)r * K + k0 + c);
        }
    };

    float acc[2][WN][4];
    #pragma unroll
    for (int i = 0; i < 2; i++)
        #pragma unroll
        for (int f = 0; f < WN; f++)
            #pragma unroll
            for (int j = 0; j < 4; j++)
                acc[i][f][j] = 0.f;

    #pragma unroll
    for (int s = 0; s < GST - 1; s++) {
        if (s < nslab) issue(s, s);
        cp_commit();
    }

    for (int i = 0; i < nslab; i++) {
        if (i + GST - 1 < nslab) cp_wait<GST - 2>(); else cp_wait<0>();
        __syncthreads();
        if (i + GST - 1 < nslab) issue((i + GST - 1) % GST, i + GST - 1);
        cp_commit();

        const float* AS = ASbase + (i % GST) * GBM * GLD;
        const float* BS = BSbase + (i % GST) * BN * GLD;
        #pragma unroll
        for (int kk = 0; kk < GBK; kk += 8) {
            uint32_t af[2][4];
            #pragma unroll
            for (int t2 = 0; t2 < 2; t2++) {
                int rbase = wm + t2 * 16;
                float2 aA = *reinterpret_cast<const float2*>(
                    &AS[(rbase + gid) * GLD + kk + 2 * tig]);
                float2 aB = *reinterpret_cast<const float2*>(
                    &AS[(rbase + 8 + gid) * GLD + kk + 2 * tig]);
                if (CVTA) {
                    af[t2][0] = f2tf(aA.x); af[t2][1] = f2tf(aB.x);
                    af[t2][2] = f2tf(aA.y); af[t2][3] = f2tf(aB.y);
                } else {
                    af[t2][0] = __float_as_uint(aA.x);
                    af[t2][1] = __float_as_uint(aB.x);
                    af[t2][2] = __float_as_uint(aA.y);
                    af[t2][3] = __float_as_uint(aB.y);
                }
            }
            #pragma unroll
            for (int f = 0; f < WN; f++) {
                float2 bb = *reinterpret_cast<const float2*>(
                    &BS[(wn + f * 8 + gid) * GLD + kk + 2 * tig]);
                uint32_t b0 = __float_as_uint(bb.x);
                uint32_t b1 = __float_as_uint(bb.y);
                mma_tf32(acc[0][f], af[0], b0, b1);
                mma_tf32(acc[1][f], af[1], b0, b1);
            }
        }
    }

    // ---- epilogue ----
    if (EPI == EPI_SOFTPL_T) {
        __syncthreads();
        float* sD = smem;
        #pragma unroll
        for (int t2 = 0; t2 < 2; t2++) {
            #pragma unroll
            for (int rr = 0; rr < 2; rr++) {
                int row = wm + t2 * 16 + gid + rr * 8;
                #pragma unroll
                for (int f = 0; f < WN; f++) {
                    int cl = wn + f * 8 + 2 * tig;
                    sD[(cl)     * 129 + row] = acc[t2][f][rr * 2 + 0];
                    sD[(cl + 1) * 129 + row] = acc[t2][f][rr * 2 + 1];
                }
            }
        }
        __syncthreads();
        int bb2 = bm >> 11, t0 = bm & (LSEQ - 1);
        for (int e = tid; e < BN * 128; e += 256) {
            int cl = e >> 7, tt = e & 127;
            float v = softplusf(sD[cl * 129 + tt] + bias[bn + cl]);
            C[((size_t)(bb2 * D_INNER) + bn + cl) * LSEQ + t0 + tt] = v;
        }
        return;
    }

    #pragma unroll
    for (int t2 = 0; t2 < 2; t2++) {
        #pragma unroll
        for (int rr = 0; rr < 2; rr++) {
            int row = bm + wm + t2 * 16 + gid + rr * 8;
            float* crow = C + (size_t)row * N;
            const float* rrow = (EPI == EPI_RESID) ? (resid + (size_t)row * N) : nullptr;
            #pragma unroll
            for (int f = 0; f < WN; f++) {
                int col = bn + wn + f * 8 + 2 * tig;
                float v0 = acc[t2][f][rr * 2 + 0];
                float v1 = acc[t2][f][rr * 2 + 1];
                if (KSPLIT > 1) {
                    int c0 = col, c1 = col + 1;
                    if (PERMC) {
                        c0 = (c0 < DT_RANK) ? permc(c0) : c0;
                        c1 = (c1 < DT_RANK) ? permc(c1) : c1;
                    }
                    atomicAdd(&crow[c0], v0);
                    atomicAdd(&crow[c1], v1);
                } else if (EPI == EPI_RND) {
                    crow[PERMC ? permc(col)     : col]     = f2tf_f(v0);
                    crow[PERMC ? permc(col + 1) : col + 1] = f2tf_f(v1);
                } else {
                    if (EPI == EPI_RESID) {
                        v0 += bias[col]     + rrow[col];
                        v1 += bias[col + 1] + rrow[col + 1];
                    } else if (EPI == EPI_BIAS) {
                        v0 += bias[col]; v1 += bias[col + 1];
                    }
                    *reinterpret_cast<float2*>(&crow[col]) = make_float2(v0, v1);
                }
            }
        }
    }
}

// ---------------- depthwise causal conv + silu, dual-layout output ----------------
__global__ __launch_bounds__(256)
void conv_silu_T_kernel(const float* __restrict__ conv_w,
                        const float* __restrict__ conv_b)
{
    __shared__ float sx[35][33];
    __shared__ float so[32][33];
    int t0 = blockIdx.x * 32, d0 = blockIdx.y * 32, b = blockIdx.z;
    int tx = threadIdx.x, ty = threadIdx.y;

    for (int r = ty; r < 35; r += 8) {
        int t = t0 - 3 + r;
        float v = (t >= 0) ? g_xz[((size_t)(b * LSEQ) + t) * (2 * D_INNER) + d0 + tx] : 0.f;
        sx[r][tx] = v;
    }
    __syncthreads();

    int d = d0 + tx;
    int dp = permc(d);
    float w0 = conv_w[d * 4 + 0], w1 = conv_w[d * 4 + 1];
    float w2 = conv_w[d * 4 + 2], w3 = conv_w[d * 4 + 3];
    float bb = conv_b[d];
    for (int r = ty; r < 32; r += 8) {
        float acc = bb;
        acc = fmaf(w0, sx[r][tx],     acc);
        acc = fmaf(w1, sx[r + 1][tx], acc);
        acc = fmaf(w2, sx[r + 2][tx], acc);
        acc = fmaf(w3, sx[r + 3][tx], acc);
        float sv = acc / (1.f + __expf(-acc));
        g_xconv[((size_t)(b * LSEQ) + t0 + r) * D_INNER + dp] = f2tf_f(sv);
        so[tx][r] = sv;
    }
    __syncthreads();

    for (int r = ty; r < 32; r += 8)
        g_uT[((size_t)(b * D_INNER) + d0 + r) * LSEQ + t0 + tx] = so[r][tx];
}

// ---------------- chunked selective scan (smem-cached B/C tile) -------------
__global__ __launch_bounds__(256)
void scan_pass1(const float* __restrict__ A_log)
{
    __shared__ float sBC[TCH][32];    // B|C tile for this chunk: 16KB
    int c = blockIdx.x, db = blockIdx.y, b = blockIdx.z;
    int n = threadIdx.x & 15, ch = threadIdx.x >> 4;
    int d = db * 16 + ch;
    int tid = threadIdx.x;

    const float* xd = g_xdbl + ((size_t)(b * LSEQ) + c * TCH) * XDBL;
    // cooperative coalesced load: cols 32..63 of each of TCH rows
    for (int e = tid; e < TCH * 8; e += 256) {
        int t = e >> 3, c4 = (e & 7) << 2;
        *reinterpret_cast<float4*>(&sBC[t][c4]) =
            *reinterpret_cast<const float4*>(&xd[(size_t)t * XDBL + 32 + c4]);
    }
    __syncthreads();

    float Av = -__expf(A_log[d * D_STATE + n]);
    const float* dTp = g_dT + ((size_t)(b * D_INNER) + d) * LSEQ + c * TCH;
    const float* uTp = g_uT + ((size_t)(b * D_INNER) + d) * LSEQ + c * TCH;

    float h = 0.f, S = 0.f;
    #pragma unroll 2
    for (int j = 0; j < TCH; j += 4) {
        float4 dv = *reinterpret_cast<const float4*>(dTp + j);
        float4 uv = *reinterpret_cast<const float4*>(uTp + j);
        float dl[4] = {dv.x, dv.y, dv.z, dv.w};
        float uu[4] = {uv.x, uv.y, uv.z, uv.w};
        #pragma unroll
        for (int q = 0; q < 4; q++) {
            float Bv = sBC[j + q][n];
            float a  = __expf(dl[q] * Av);
            h = fmaf(a, h, dl[q] * uu[q] * Bv);
            S += dl[q];
        }
    }
    g_hchk[(((size_t)(b * D_INNER) + d) * CS + c) * D_STATE + n] = h;
    if (n == 0)
        g_schk[((size_t)(b * D_INNER) + d) * CS + c] = S;
}

__global__ void scan_combine(const float* __restrict__ A_log)
{
    int idx = blockIdx.x * blockDim.x + threadIdx.x;
    if (idx >= BATCH * D_INNER * D_STATE) return;
    int n = idx & 15;
    int d = (idx >> 4) & (D_INNER - 1);
    int b = idx >> 14;
    float Av = -__expf(A_log[d * D_STATE + n]);
    size_t base = ((size_t)(b * D_INNER) + d) * CS;
    float h0 = 0.f;
    #pragma unroll
    for (int c = 0; c < CS; c++) {
        g_h0[(base + c) * D_STATE + n] = h0;
        float S = g_schk[base + c];
        h0 = g_hchk[(base + c) * D_STATE + n] + __expf(Av * S) * h0;
    }
}

__global__ __launch_bounds__(256)
void scan_pass2(const float* __restrict__ A_log, const float* __restrict__ Dv)
{
    __shared__ float sBC[TCH][32];    // B|C tile: 16KB
    int c = blockIdx.x, db = blockIdx.y, b = blockIdx.z;
    int n = threadIdx.x & 15, ch = threadIdx.x >> 4;
    int d = db * 16 + ch;
    int tid = threadIdx.x;

    const float* xd = g_xdbl + ((size_t)(b * LSEQ) + c * TCH) * XDBL;
    for (int e = tid; e < TCH * 8; e += 256) {
        int t = e >> 3, c4 = (e & 7) << 2;
        *reinterpret_cast<float4*>(&sBC[t][c4]) =
            *reinterpret_cast<const float4*>(&xd[(size_t)t * XDBL + 32 + c4]);
    }
    __syncthreads();

    float Av = -__expf(A_log[d * D_STATE + n]);
    float Dd = Dv[d];

    const float* dTp = g_dT + ((size_t)(b * D_INNER) + d) * LSEQ + c * TCH;
    const float* uTp = g_uT + ((size_t)(b * D_INNER) + d) * LSEQ + c * TCH;
    const float* zP  = g_xz + ((size_t)(b * LSEQ) + c * TCH) * (2 * D_INNER) + D_INNER + d;
    float* yP = g_yscan + ((size_t)(b * LSEQ) + c * TCH) * D_INNER + permc(d);

    float h = g_h0[(((size_t)(b * D_INNER) + d) * CS + c) * D_STATE + n];

    #pragma unroll 2
    for (int j = 0; j < TCH; j += 4) {
        float4 dv = *reinterpret_cast<const float4*>(dTp + j);
        float4 uv = *reinterpret_cast<const float4*>(uTp + j);
        float dl[4] = {dv.x, dv.y, dv.z, dv.w};
        float uu[4] = {uv.x, uv.y, uv.z, uv.w};
        #pragma unroll
        for (int q = 0; q < 4; q++) {
            float Bv = sBC[j + q][n];
            float Cv = sBC[j + q][16 + n];
            float a  = __expf(dl[q] * Av);
            h = fmaf(a, h, dl[q] * uu[q] * Bv);
            float p = h * Cv;
            #pragma unroll
            for (int o = 8; o; o >>= 1)
                p += __shfl_xor_sync(0xffffffffu, p, o);
            if (n == 0) {
                float z = zP[(size_t)(j + q) * (2 * D_INNER)];
                float sig = z / (1.f + __expf(-z));
                yP[(size_t)(j + q) * D_INNER] = f2tf_f((p + uu[q] * Dd) * sig);
            }
        }
    }
}

// ---------------- launch ----------------
static float* sym(const void* symbol) {
    void* p = nullptr;
    cudaGetSymbolAddress(&p, symbol);
    return (float*)p;
}

extern "C" void kernel_launch(void* const* d_in, const int* in_sizes, int n_in,
                              void* d_out, int out_size)
{
    const float* x         = (const float*)d_in[0];
    const float* norm_w    = (const float*)d_in[1];
    const float* norm_b    = (const float*)d_in[2];
    const float* in_proj_w = (const float*)d_in[3];
    const float* conv_w    = (const float*)d_in[4];
    const float* conv_b    = (const float*)d_in[5];
    const float* x_proj_w  = (const float*)d_in[6];
    const float* dt_proj_w = (const float*)d_in[7];
    const float* dt_proj_b = (const float*)d_in[8];
    const float* A_log     = (const float*)d_in[9];
    const float* Dv        = (const float*)d_in[10];
    const float* mix_out_w = (const float*)d_in[11];
    const float* match_w   = (const float*)d_in[12];
    const float* match_b   = (const float*)d_in[13];
    const float* geom_w    = (const float*)d_in[14];
    const float* geom_b    = (const float*)d_in[15];
    const float* normm_w   = (const float*)d_in[16];
    const float* normm_b   = (const float*)d_in[17];
    const float* normg_w   = (const float*)d_in[18];
    const float* normg_b   = (const float*)d_in[19];

    float* p_hln   = sym(g_hln);
    float* p_xdbl  = sym(g_xdbl);
    float* p_xz    = sym(g_xz);
    float* p_xconv = sym(g_xconv);
    float* p_dT    = sym(g_dT);
    float* p_yscan = sym(g_yscan);
    float* p_hout  = sym(g_hout);
    float* p_match = sym(g_match);
    float* p_geom  = sym(g_geom);
    float* p_wip   = sym(g_wip);
    float* p_wxp   = sym(g_wxp);
    float* p_wdt   = sym(g_wdt);
    float* p_wmo   = sym(g_wmo);
    float* p_wma   = sym(g_wma);
    float* p_wge   = sym(g_wge);

    float* out_match = (float*)d_out;
    float* out_geom  = (float*)d_out + (size_t)NROWS * DIM;

    // dynamic smem opt-in (idempotent)
    cudaFuncSetAttribute(tgemm_kernel<128, EPI_NONE, 1, false, false>,
                         cudaFuncAttributeMaxDynamicSharedMemorySize, GEMM_SMEM(128));
    cudaFuncSetAttribute(tgemm_kernel<64, EPI_NONE, 4, false, true>,
                         cudaFuncAttributeMaxDynamicSharedMemorySize, GEMM_SMEM(64));
    cudaFuncSetAttribute(tgemm_kernel<64, EPI_SOFTPL_T, 1, true, false>,
                         cudaFuncAttributeMaxDynamicSharedMemorySize, GEMM_SMEM(64));
    cudaFuncSetAttribute(tgemm_kernel<64, EPI_RND, 1, false, true>,
                         cudaFuncAttributeMaxDynamicSharedMemorySize, GEMM_SMEM(64));
    cudaFuncSetAttribute(tgemm_kernel<64, EPI_RESID, 1, false, false>,
                         cudaFuncAttributeMaxDynamicSharedMemorySize, GEMM_SMEM(64));
    cudaFuncSetAttribute(tgemm_kernel<64, EPI_BIAS, 1, false, false>,
                         cudaFuncAttributeMaxDynamicSharedMemorySize, GEMM_SMEM(64));

    // kernel order: #4 = in_proj (ncu)
    {
        int total = W_XP + W_DT + W_MO + W_MA + W_GE;
        round_wrest_kernel<<<(total + 255) / 256, 256>>>(x_proj_w, dt_proj_w,
                                                         mix_out_w, match_w, geom_w);
    }
    layernorm_kernel<true><<<NROWS, 256>>>(x, norm_w, norm_b, p_hln, DIM);
    round_wip_kernel<<<(W_IP + 255) / 256, 256>>>(in_proj_w);

    // 4. xz = h @ in_proj_w^T   [8192, 2048] K=512  (BN=128, 1024 CTAs)
    {
        dim3 grid(2 * D_INNER / 128, NROWS / GBM);
        tgemm_kernel<128, EPI_NONE, 1, false, false><<<grid, 256, GEMM_SMEM(128)>>>(
            p_hln, DIM, p_wip, nullptr, nullptr, p_xz, NROWS, 2 * D_INNER, DIM);
    }

    // 5. u = silu(conv(xm))
    {
        dim3 grid(LSEQ / 32, D_INNER / 32, BATCH);
        conv_silu_T_kernel<<<grid, dim3(32, 8)>>>(conv_w, conv_b);
    }

    // 6. x_dbl = u @ x_proj_w^T [8192,64] K=1024, split-K=4 (BN=64)
    cudaMemsetAsync(p_xdbl, 0, (size_t)NROWS * XDBL * sizeof(float));
    {
        dim3 grid(1, NROWS / GBM, 4);
        tgemm_kernel<64, EPI_NONE, 4, false, true><<<grid, 256, GEMM_SMEM(64)>>>(
            p_xconv, D_INNER, p_wxp, nullptr, nullptr, p_xdbl, NROWS, XDBL, D_INNER);
    }

    // 7. deltaT = softplus(...), smem-transposed coalesced store (BN=64, 1024 CTAs)
    {
        dim3 grid(D_INNER / 64, NROWS / GBM);
        tgemm_kernel<64, EPI_SOFTPL_T, 1, true, false><<<grid, 256, GEMM_SMEM(64)>>>(
            p_xdbl, XDBL, p_wdt, dt_proj_b, nullptr, p_dT, NROWS, D_INNER, DT_RANK);
    }

    // 8/9/10. chunked selective scan (smem B/C tiles)
    {
        dim3 grid(CS, D_INNER / 16, BATCH);
        scan_pass1<<<grid, 256>>>(A_log);
        scan_combine<<<(BATCH * D_INNER * D_STATE) / 256, 256>>>(A_log);
        scan_pass2<<<grid, 256>>>(A_log, Dv);
    }

    // 11. h_out = y @ mix_out_w^T (BN=64, 512 CTAs; rounds+permutes)
    {
        dim3 grid(DIM / 64, NROWS / GBM);
        tgemm_kernel<64, EPI_RND, 1, false, true><<<grid, 256, GEMM_SMEM(64)>>>(
            p_yscan, D_INNER, p_wmo, nullptr, nullptr, p_hout, NROWS, DIM, D_INNER);
    }

    // 12. match_pre = residual + h_out @ match_w^T + match_b (BN=64, 512 CTAs)
    {
        dim3 grid(DIM / 64, NROWS / GBM);
        tgemm_kernel<64, EPI_RESID, 1, false, false><<<grid, 256, GEMM_SMEM(64)>>>(
            p_hout, DIM, p_wma, match_b, x, p_match, NROWS, DIM, DIM);
    }

    // 13. geom_pre = h_out @ geom_w^T + geom_b (BN=64, 256 CTAs)
    {
        dim3 grid(D_GEOM / 64, NROWS / GBM);
        tgemm_kernel<64, EPI_BIAS, 1, false, false><<<grid, 256, GEMM_SMEM(64)>>>(
            p_hout, DIM, p_wge, geom_b, nullptr, p_geom, NROWS, D_GEOM, DIM);
    }

    // 14/15. final layernorms into d_out
    layernorm_kernel<false><<<NROWS, 256>>>(p_match, normm_w, normm_b, out_match, DIM);
    layernorm_kernel<false><<<NROWS, 256>>>(p_geom,  normg_w, normg_b, out_geom,  D_GEOM);
}

// round 13
// speedup vs baseline: 1.4636x; 1.3348x over previous
#include <cuda_runtime.h>
#include <cuda_bf16.h>
#include <cstdint>

// ---------------- problem constants ----------------
#define BATCH   4
#define LSEQ    2048
#define NROWS   (BATCH*LSEQ)        // 8192
#define DIM     512
#define D_INNER 1024
#define D_STATE 16
#define D_CONV  4
#define DT_RANK 32
#define XDBL    (DT_RANK + 2*D_STATE)  // 64
#define D_GEOM  256
#define EPSV    1e-5f
#define CS      16                   // scan chunks
#define TCH     (LSEQ/CS)            // 128 steps per chunk

#define W_IP (2*D_INNER*DIM)
#define W_XP (XDBL*D_INNER)
#define W_DT (D_INNER*DT_RANK)
#define W_MO (DIM*D_INNER)
#define W_MA (DIM*DIM)
#define W_GE (D_GEOM*DIM)

// ---------------- scratch (device globals; no allocation) ----------------
__device__ float g_hln  [NROWS * DIM];            // permuted k-layout
__device__ float g_xz   [NROWS * 2 * D_INNER];
__device__ float g_xconv[NROWS * D_INNER];        // permuted + rounded
__device__ float g_uT   [BATCH * D_INNER * LSEQ];
__device__ float g_dT   [BATCH * D_INNER * LSEQ];
__device__ float g_xdbl [NROWS * XDBL];           // cols<32 permuted
__device__ float g_yscan[NROWS * D_INNER];        // permuted + rounded
__device__ float g_hout [NROWS * DIM];            // permuted + rounded
__device__ float g_match[NROWS * DIM];
__device__ float g_geom [NROWS * D_GEOM];
__device__ float g_hchk [BATCH * D_INNER * CS * D_STATE];
__device__ float g_schk [BATCH * D_INNER * CS];
__device__ float g_h0   [BATCH * D_INNER * CS * D_STATE];
__device__ float g_wip[W_IP];   // all weights: permuted + rounded
__device__ float g_wxp[W_XP];
__device__ float g_wdt[W_DT];
__device__ float g_wmo[W_MO];
__device__ float g_wma[W_MA];
__device__ float g_wge[W_GE];

__device__ __forceinline__ uint32_t f2tf(float f) {
    uint32_t r; asm("cvt.rna.tf32.f32 %0, %1;" : "=r"(r) : "f"(f)); return r;
}
__device__ __forceinline__ float f2tf_f(float f) {
    return __uint_as_float(f2tf(f));
}
__device__ __forceinline__ float softplusf(float v) {
    return (v > 20.f) ? v : log1pf(__expf(v));
}
// k-permutation within 8-blocks: position(k) = 2*(k%4) + (k/4)%2
__device__ __forceinline__ int permc(int c) {
    return (c & ~7) | (((c & 3) << 1) | ((c >> 2) & 1));
}

__device__ __forceinline__ void cp16(uint32_t daddr, const void* gptr) {
    asm volatile("cp.async.cg.shared.global [%0], [%1], 16;" :: "r"(daddr), "l"(gptr));
}
__device__ __forceinline__ void cp_commit() {
    asm volatile("cp.async.commit_group;");
}
template<int N>
__device__ __forceinline__ void cp_wait() {
    asm volatile("cp.async.wait_group %0;" :: "n"(N));
}

__device__ __forceinline__ void mma_tf32(float* c, const uint32_t* a,
                                         uint32_t b0, uint32_t b1) {
    asm volatile(
        "mma.sync.aligned.m16n8k8.row.col.f32.tf32.tf32.f32 "
        "{%0,%1,%2,%3}, {%4,%5,%6,%7}, {%8,%9}, {%0,%1,%2,%3};"
        : "+f"(c[0]), "+f"(c[1]), "+f"(c[2]), "+f"(c[3])
        : "r"(a[0]), "r"(a[1]), "r"(a[2]), "r"(a[3]), "r"(b0), "r"(b1));
}

// ---------------- weight pre-rounding + permutation ----------------
__global__ void round_wip_kernel(const float* __restrict__ ip)
{
    int i = blockIdx.x * blockDim.x + threadIdx.x;
    if (i >= W_IP) return;
    int r = i / DIM, k = i % DIM;
    g_wip[r * DIM + permc(k)] = f2tf_f(ip[i]);
}
__global__ void round_wrest_kernel(const float* __restrict__ xp,
                                   const float* __restrict__ dt,
                                   const float* __restrict__ mo,
                                   const float* __restrict__ ma,
                                   const float* __restrict__ ge)
{
    int i = blockIdx.x * blockDim.x + threadIdx.x;
    int total = W_XP + W_DT + W_MO + W_MA + W_GE;
    if (i >= total) return;
    if (i < W_XP) { int r = i / D_INNER, k = i % D_INNER;
        g_wxp[r * D_INNER + permc(k)] = f2tf_f(xp[i]); return; }
    i -= W_XP;
    if (i < W_DT) { int r = i / DT_RANK, k = i % DT_RANK;
        g_wdt[r * DT_RANK + permc(k)] = f2tf_f(dt[i]); return; }
    i -= W_DT;
    if (i < W_MO) { int r = i / D_INNER, k = i % D_INNER;
        g_wmo[r * D_INNER + permc(k)] = f2tf_f(mo[i]); return; }
    i -= W_MO;
    if (i < W_MA) { int r = i / DIM, k = i % DIM;
        g_wma[r * DIM + permc(k)] = f2tf_f(ma[i]); return; }
    i -= W_MA;
    { int r = i / DIM, k = i % DIM;
      g_wge[r * DIM + permc(k)] = f2tf_f(ge[i]); }
}

// ---------------- layernorm ----------------
template<bool RNDPERM>
__global__ void layernorm_kernel(const float* __restrict__ in,
                                 const float* __restrict__ w,
                                 const float* __restrict__ b,
                                 float* __restrict__ out, int cols)
{
    int row = blockIdx.x;
    const float* p = in + (size_t)row * cols;
    float s = 0.f, sq = 0.f;
    for (int c = threadIdx.x; c < cols; c += blockDim.x) {
        float v = p[c]; s += v; sq += v * v;
    }
    int lane = threadIdx.x & 31, wid = threadIdx.x >> 5;
    #pragma unroll
    for (int o = 16; o; o >>= 1) {
        s  += __shfl_xor_sync(0xffffffffu, s,  o);
        sq += __shfl_xor_sync(0xffffffffu, sq, o);
    }
    __shared__ float shs[8], shq[8];
    if (!lane) { shs[wid] = s; shq[wid] = sq; }
    __syncthreads();
    if (threadIdx.x == 0) {
        float ts = 0.f, tq = 0.f;
        int nw = (blockDim.x + 31) >> 5;
        for (int i = 0; i < nw; i++) { ts += shs[i]; tq += shq[i]; }
        float mu  = ts / cols;
        float var = tq / cols - mu * mu;
        shs[0] = mu;
        shq[0] = rsqrtf(var + EPSV);
    }
    __syncthreads();
    float mu = shs[0], inv = shq[0];
    float* o = out + (size_t)row * cols;
    for (int c = threadIdx.x; c < cols; c += blockDim.x) {
        float v = (p[c] - mu) * inv * w[c] + b[c];
        if (RNDPERM) o[permc(c)] = f2tf_f(v);
        else         o[c] = v;
    }
}

// ---------------- tf32 mma.sync GEMM, cp.async 3-stage, 128xBN tile ----------
#define EPI_NONE      0
#define EPI_RESID     2
#define EPI_BIAS      3
#define EPI_SOFTPL_T  4
#define EPI_RND       5

#define GBM 128
#define GBK 16
#define GLD 24
#define GST 3
#define GEMM_SMEM(BN) (GST * (GBM + (BN)) * GLD * 4)

template<int BN, int EPI, int KSPLIT, bool CVTA, bool PERMC>
__global__ __launch_bounds__(256, (BN == 64) ? 3 : 2)
void tgemm_kernel(const float* __restrict__ A, int lda,
                  const float* __restrict__ B,
                  const float* __restrict__ bias,
                  const float* __restrict__ resid,
                  float* __restrict__ C,
                  int M, int N, int K)
{
    const int WN = BN / 16;
    extern __shared__ float smem[];
    float* ASbase = smem;
    float* BSbase = smem + GST * GBM * GLD;

    const int tid  = threadIdx.x;
    const int wid  = tid >> 5;
    const int lane = tid & 31;
    const int gid  = lane >> 2;
    const int tig  = lane & 3;
    const int wm   = (wid & 3) * 32;
    const int wn   = (wid >> 2) * (BN / 2);
    const int bm   = blockIdx.y * GBM;
    const int bn   = blockIdx.x * BN;

    const int kchunk = K / KSPLIT;
    const int kbeg   = (KSPLIT > 1) ? blockIdx.z * kchunk : 0;
    const int nslab  = kchunk / GBK;

    const float* Ag = A + (size_t)bm * lda + kbeg;
    const float* Bg = B + (size_t)bn * K + kbeg;

    const uint32_t sA = (uint32_t)__cvta_generic_to_shared(ASbase);
    const uint32_t sB = (uint32_t)__cvta_generic_to_shared(BSbase);

    auto issue = [&](int stage, int slab) {
        int k0 = slab * GBK;
        #pragma unroll
        for (int i = 0; i < 2; i++) {
            int id = tid + i * 256;
            int r = id >> 2, c = (id & 3) << 2;
            cp16(sA + (uint32_t)((stage * GBM + r) * GLD + c) * 4,
                 Ag + (size_t)r * lda + k0 + c);
        }
        #pragma unroll
        for (int i = 0; i < BN / 64; i++) {
            int id = tid + i * 256;
            int r = id >> 2, c = (id & 3) << 2;
            cp16(sB + (uint32_t)((stage * BN + r) * GLD + c) * 4,
                 Bg + (size_t)r * K + k0 + c);
        }
    };

    float acc[2][WN][4];
    #pragma unroll
    for (int i = 0; i < 2; i++)
        #pragma unroll
        for (int f = 0; f < WN; f++)
            #pragma unroll
            for (int j = 0; j < 4; j++)
                acc[i][f][j] = 0.f;

    #pragma unroll
    for (int s = 0; s < GST - 1; s++) {
        if (s < nslab) issue(s, s);
        cp_commit();
    }

    for (int i = 0; i < nslab; i++) {
        if (i + GST - 1 < nslab) cp_wait<GST - 2>(); else cp_wait<0>();
        __syncthreads();
        if (i + GST - 1 < nslab) issue((i + GST - 1) % GST, i + GST - 1);
        cp_commit();

        const float* AS = ASbase + (i % GST) * GBM * GLD;
        const float* BS = BSbase + (i % GST) * BN * GLD;
        #pragma unroll
        for (int kk = 0; kk < GBK; kk += 8) {
            uint32_t af[2][4];
            #pragma unroll
            for (int t2 = 0; t2 < 2; t2++) {
                int rbase = wm + t2 * 16;
                float2 aA = *reinterpret_cast<const float2*>(
                    &AS[(rbase + gid) * GLD + kk + 2 * tig]);
                float2 aB = *reinterpret_cast<const float2*>(
                    &AS[(rbase + 8 + gid) * GLD + kk + 2 * tig]);
                if (CVTA) {
                    af[t2][0] = f2tf(aA.x); af[t2][1] = f2tf(aB.x);
                    af[t2][2] = f2tf(aA.y); af[t2][3] = f2tf(aB.y);
                } else {
                    af[t2][0] = __float_as_uint(aA.x);
                    af[t2][1] = __float_as_uint(aB.x);
                    af[t2][2] = __float_as_uint(aA.y);
                    af[t2][3] = __float_as_uint(aB.y);
                }
            }
            #pragma unroll
            for (int f = 0; f < WN; f++) {
                float2 bb = *reinterpret_cast<const float2*>(
                    &BS[(wn + f * 8 + gid) * GLD + kk + 2 * tig]);
                uint32_t b0 = __float_as_uint(bb.x);
                uint32_t b1 = __float_as_uint(bb.y);
                mma_tf32(acc[0][f], af[0], b0, b1);
                mma_tf32(acc[1][f], af[1], b0, b1);
            }
        }
    }

    // ---- epilogue ----
    if (EPI == EPI_SOFTPL_T) {
        __syncthreads();
        float* sD = smem;
        #pragma unroll
        for (int t2 = 0; t2 < 2; t2++) {
            #pragma unroll
            for (int rr = 0; rr < 2; rr++) {
                int row = wm + t2 * 16 + gid + rr * 8;
                #pragma unroll
                for (int f = 0; f < WN; f++) {
                    int cl = wn + f * 8 + 2 * tig;
                    sD[(cl)     * 129 + row] = acc[t2][f][rr * 2 + 0];
                    sD[(cl + 1) * 129 + row] = acc[t2][f][rr * 2 + 1];
                }
            }
        }
        __syncthreads();
        int bb2 = bm >> 11, t0 = bm & (LSEQ - 1);
        for (int e = tid; e < BN * 128; e += 256) {
            int cl = e >> 7, tt = e & 127;
            float v = softplusf(sD[cl * 129 + tt] + bias[bn + cl]);
            C[((size_t)(bb2 * D_INNER) + bn + cl) * LSEQ + t0 + tt] = v;
        }
        return;
    }

    #pragma unroll
    for (int t2 = 0; t2 < 2; t2++) {
        #pragma unroll
        for (int rr = 0; rr < 2; rr++) {
            int row = bm + wm + t2 * 16 + gid + rr * 8;
            float* crow = C + (size_t)row * N;
            const float* rrow = (EPI == EPI_RESID) ? (resid + (size_t)row * N) : nullptr;
            #pragma unroll
            for (int f = 0; f < WN; f++) {
                int col = bn + wn + f * 8 + 2 * tig;
                float v0 = acc[t2][f][rr * 2 + 0];
                float v1 = acc[t2][f][rr * 2 + 1];
                if (KSPLIT > 1) {
                    int c0 = col, c1 = col + 1;
                    if (PERMC) {
                        c0 = (c0 < DT_RANK) ? permc(c0) : c0;
                        c1 = (c1 < DT_RANK) ? permc(c1) : c1;
                    }
                    atomicAdd(&crow[c0], v0);
                    atomicAdd(&crow[c1], v1);
                } else if (EPI == EPI_RND) {
                    crow[PERMC ? permc(col)     : col]     = f2tf_f(v0);
                    crow[PERMC ? permc(col + 1) : col + 1] = f2tf_f(v1);
                } else {
                    if (EPI == EPI_RESID) {
                        v0 += bias[col]     + rrow[col];
                        v1 += bias[col + 1] + rrow[col + 1];
                    } else if (EPI == EPI_BIAS) {
                        v0 += bias[col]; v1 += bias[col + 1];
                    }
                    *reinterpret_cast<float2*>(&crow[col]) = make_float2(v0, v1);
                }
            }
        }
    }
}

// ---------------- depthwise causal conv + silu, dual-layout output ----------------
__global__ __launch_bounds__(256)
void conv_silu_T_kernel(const float* __restrict__ conv_w,
                        const float* __restrict__ conv_b)
{
    __shared__ float sx[35][33];
    __shared__ float so[32][33];
    int t0 = blockIdx.x * 32, d0 = blockIdx.y * 32, b = blockIdx.z;
    int tx = threadIdx.x, ty = threadIdx.y;

    for (int r = ty; r < 35; r += 8) {
        int t = t0 - 3 + r;
        float v = (t >= 0) ? g_xz[((size_t)(b * LSEQ) + t) * (2 * D_INNER) + d0 + tx] : 0.f;
        sx[r][tx] = v;
    }
    __syncthreads();

    int d = d0 + tx;
    int dp = permc(d);
    float w0 = conv_w[d * 4 + 0], w1 = conv_w[d * 4 + 1];
    float w2 = conv_w[d * 4 + 2], w3 = conv_w[d * 4 + 3];
    float bb = conv_b[d];
    for (int r = ty; r < 32; r += 8) {
        float acc = bb;
        acc = fmaf(w0, sx[r][tx],     acc);
        acc = fmaf(w1, sx[r + 1][tx], acc);
        acc = fmaf(w2, sx[r + 2][tx], acc);
        acc = fmaf(w3, sx[r + 3][tx], acc);
        float sv = acc / (1.f + __expf(-acc));
        g_xconv[((size_t)(b * LSEQ) + t0 + r) * D_INNER + dp] = f2tf_f(sv);
        so[tx][r] = sv;
    }
    __syncthreads();

    for (int r = ty; r < 32; r += 8)
        g_uT[((size_t)(b * D_INNER) + d0 + r) * LSEQ + t0 + tx] = so[r][tx];
}

// ---------------- chunked selective scan (smem-cached tiles) ---------------
__global__ __launch_bounds__(256)
void scan_pass1(const float* __restrict__ A_log)
{
    __shared__ float sBC[TCH][32];    // B|C tile for this chunk: 16KB
    int c = blockIdx.x, db = blockIdx.y, b = blockIdx.z;
    int n = threadIdx.x & 15, ch = threadIdx.x >> 4;
    int d = db * 16 + ch;
    int tid = threadIdx.x;

    const float* xd = g_xdbl + ((size_t)(b * LSEQ) + c * TCH) * XDBL;
    for (int e = tid; e < TCH * 8; e += 256) {
        int t = e >> 3, c4 = (e & 7) << 2;
        *reinterpret_cast<float4*>(&sBC[t][c4]) =
            *reinterpret_cast<const float4*>(&xd[(size_t)t * XDBL + 32 + c4]);
    }
    __syncthreads();

    float Av = -__expf(A_log[d * D_STATE + n]);
    const float* dTp = g_dT + ((size_t)(b * D_INNER) + d) * LSEQ + c * TCH;
    const float* uTp = g_uT + ((size_t)(b * D_INNER) + d) * LSEQ + c * TCH;

    float h = 0.f, S = 0.f;
    #pragma unroll 2
    for (int j = 0; j < TCH; j += 4) {
        float4 dv = *reinterpret_cast<const float4*>(dTp + j);
        float4 uv = *reinterpret_cast<const float4*>(uTp + j);
        float dl[4] = {dv.x, dv.y, dv.z, dv.w};
        float uu[4] = {uv.x, uv.y, uv.z, uv.w};
        #pragma unroll
        for (int q = 0; q < 4; q++) {
            float Bv = sBC[j + q][n];
            float a  = __expf(dl[q] * Av);
            h = fmaf(a, h, dl[q] * uu[q] * Bv);
            S += dl[q];
        }
    }
    g_hchk[(((size_t)(b * D_INNER) + d) * CS + c) * D_STATE + n] = h;
    if (n == 0)
        g_schk[((size_t)(b * D_INNER) + d) * CS + c] = S;
}

__global__ void scan_combine(const float* __restrict__ A_log)
{
    int idx = blockIdx.x * blockDim.x + threadIdx.x;
    if (idx >= BATCH * D_INNER * D_STATE) return;
    int n = idx & 15;
    int d = (idx >> 4) & (D_INNER - 1);
    int b = idx >> 14;
    float Av = -__expf(A_log[d * D_STATE + n]);
    size_t base = ((size_t)(b * D_INNER) + d) * CS;
    float h0 = 0.f;
    #pragma unroll
    for (int c = 0; c < CS; c++) {
        g_h0[(base + c) * D_STATE + n] = h0;
        float S = g_schk[base + c];
        h0 = g_hchk[(base + c) * D_STATE + n] + __expf(Av * S) * h0;
    }
}

__global__ __launch_bounds__(256)
void scan_pass2(const float* __restrict__ A_log, const float* __restrict__ Dv)
{
    __shared__ float sBC[TCH][32];    // B|C tile: 16KB
    __shared__ float sZ[TCH][16];     // z tile:   8KB
    __shared__ float sY[TCH][16];     // y tile:   8KB
    int c = blockIdx.x, db = blockIdx.y, b = blockIdx.z;
    int n = threadIdx.x & 15, ch = threadIdx.x >> 4;
    int d = db * 16 + ch;
    int d0g = db * 16;
    int tid = threadIdx.x;

    const float* xd = g_xdbl + ((size_t)(b * LSEQ) + c * TCH) * XDBL;
    for (int e = tid; e < TCH * 8; e += 256) {
        int t = e >> 3, c4 = (e & 7) << 2;
        *reinterpret_cast<float4*>(&sBC[t][c4]) =
            *reinterpret_cast<const float4*>(&xd[(size_t)t * XDBL + 32 + c4]);
    }
    // cooperative coalesced z load: 64B contiguous per (t)
    const float* zbase = g_xz + ((size_t)(b * LSEQ) + c * TCH) * (2 * D_INNER)
                       + D_INNER + d0g;
    for (int e = tid; e < TCH * 4; e += 256) {
        int t = e >> 2, c4 = (e & 3) << 2;
        *reinterpret_cast<float4*>(&sZ[t][c4]) =
            *reinterpret_cast<const float4*>(&zbase[(size_t)t * (2 * D_INNER) + c4]);
    }
    __syncthreads();

    float Av = -__expf(A_log[d * D_STATE + n]);
    float Dd = Dv[d];

    const float* dTp = g_dT + ((size_t)(b * D_INNER) + d) * LSEQ + c * TCH;
    const float* uTp = g_uT + ((size_t)(b * D_INNER) + d) * LSEQ + c * TCH;

    float h = g_h0[(((size_t)(b * D_INNER) + d) * CS + c) * D_STATE + n];

    #pragma unroll 2
    for (int j = 0; j < TCH; j += 4) {
        float4 dv = *reinterpret_cast<const float4*>(dTp + j);
        float4 uv = *reinterpret_cast<const float4*>(uTp + j);
        float dl[4] = {dv.x, dv.y, dv.z, dv.w};
        float uu[4] = {uv.x, uv.y, uv.z, uv.w};
        #pragma unroll
        for (int q = 0; q < 4; q++) {
            float Bv = sBC[j + q][n];
            float Cv = sBC[j + q][16 + n];
            float a  = __expf(dl[q] * Av);
            h = fmaf(a, h, dl[q] * uu[q] * Bv);
            float p = h * Cv;
            #pragma unroll
            for (int o = 8; o; o >>= 1)
                p += __shfl_xor_sync(0xffffffffu, p, o);
            if (n == 0) {
                float z = sZ[j + q][ch];
                float sig = z / (1.f + __expf(-z));
                sY[j + q][ch] = (p + uu[q] * Dd) * sig;
            }
        }
    }
    __syncthreads();

    // cooperative coalesced y store (permuted + rounded); permc stays within
    // the 16-col group because d0g is 16-aligned.
    float* ybase = g_yscan + ((size_t)(b * LSEQ) + c * TCH) * D_INNER + d0g;
    for (int e = tid; e < TCH * 16; e += 256) {
        int t = e >> 4, dd = e & 15;
        ybase[(size_t)t * D_INNER + permc(dd)] = f2tf_f(sY[t][dd]);
    }
}

// ---------------- launch ----------------
static float* sym(const void* symbol) {
    void* p = nullptr;
    cudaGetSymbolAddress(&p, symbol);
    return (float*)p;
}

extern "C" void kernel_launch(void* const* d_in, const int* in_sizes, int n_in,
                              void* d_out, int out_size)
{
    const float* x         = (const float*)d_in[0];
    const float* norm_w    = (const float*)d_in[1];
    const float* norm_b    = (const float*)d_in[2];
    const float* in_proj_w = (const float*)d_in[3];
    const float* conv_w    = (const float*)d_in[4];
    const float* conv_b    = (const float*)d_in[5];
    const float* x_proj_w  = (const float*)d_in[6];
    const float* dt_proj_w = (const float*)d_in[7];
    const float* dt_proj_b = (const float*)d_in[8];
    const float* A_log     = (const float*)d_in[9];
    const float* Dv        = (const float*)d_in[10];
    const float* mix_out_w = (const float*)d_in[11];
    const float* match_w   = (const float*)d_in[12];
    const float* match_b   = (const float*)d_in[13];
    const float* geom_w    = (const float*)d_in[14];
    const float* geom_b    = (const float*)d_in[15];
    const float* normm_w   = (const float*)d_in[16];
    const float* normm_b   = (const float*)d_in[17];
    const float* normg_w   = (const float*)d_in[18];
    const float* normg_b   = (const float*)d_in[19];

    float* p_hln   = sym(g_hln);
    float* p_xdbl  = sym(g_xdbl);
    float* p_xz    = sym(g_xz);
    float* p_xconv = sym(g_xconv);
    float* p_dT    = sym(g_dT);
    float* p_yscan = sym(g_yscan);
    float* p_hout  = sym(g_hout);
    float* p_match = sym(g_match);
    float* p_geom  = sym(g_geom);
    float* p_wip   = sym(g_wip);
    float* p_wxp   = sym(g_wxp);
    float* p_wdt   = sym(g_wdt);
    float* p_wmo   = sym(g_wmo);
    float* p_wma   = sym(g_wma);
    float* p_wge   = sym(g_wge);

    float* out_match = (float*)d_out;
    float* out_geom  = (float*)d_out + (size_t)NROWS * DIM;

    // dynamic smem opt-in (idempotent)
    cudaFuncSetAttribute(tgemm_kernel<128, EPI_NONE, 1, false, false>,
                         cudaFuncAttributeMaxDynamicSharedMemorySize, GEMM_SMEM(128));
    cudaFuncSetAttribute(tgemm_kernel<64, EPI_NONE, 4, false, true>,
                         cudaFuncAttributeMaxDynamicSharedMemorySize, GEMM_SMEM(64));
    cudaFuncSetAttribute(tgemm_kernel<64, EPI_SOFTPL_T, 1, true, false>,
                         cudaFuncAttributeMaxDynamicSharedMemorySize, GEMM_SMEM(64));
    cudaFuncSetAttribute(tgemm_kernel<64, EPI_RND, 1, false, true>,
                         cudaFuncAttributeMaxDynamicSharedMemorySize, GEMM_SMEM(64));
    cudaFuncSetAttribute(tgemm_kernel<64, EPI_RESID, 1, false, false>,
                         cudaFuncAttributeMaxDynamicSharedMemorySize, GEMM_SMEM(64));
    cudaFuncSetAttribute(tgemm_kernel<64, EPI_BIAS, 1, false, false>,
                         cudaFuncAttributeMaxDynamicSharedMemorySize, GEMM_SMEM(64));

    // kernel order: #4 = in_proj (ncu)
    {
        int total = W_XP + W_DT + W_MO + W_MA + W_GE;
        round_wrest_kernel<<<(total + 255) / 256, 256>>>(x_proj_w, dt_proj_w,
                                                         mix_out_w, match_w, geom_w);
    }
    layernorm_kernel<true><<<NROWS, 256>>>(x, norm_w, norm_b, p_hln, DIM);
    round_wip_kernel<<<(W_IP + 255) / 256, 256>>>(in_proj_w);

    // 4. xz = h @ in_proj_w^T   [8192, 2048] K=512  (BN=128, 1024 CTAs)
    {
        dim3 grid(2 * D_INNER / 128, NROWS / GBM);
        tgemm_kernel<128, EPI_NONE, 1, false, false><<<grid, 256, GEMM_SMEM(128)>>>(
            p_hln, DIM, p_wip, nullptr, nullptr, p_xz, NROWS, 2 * D_INNER, DIM);
    }

    // 5. u = silu(conv(xm))
    {
        dim3 grid(LSEQ / 32, D_INNER / 32, BATCH);
        conv_silu_T_kernel<<<grid, dim3(32, 8)>>>(conv_w, conv_b);
    }

    // 6. x_dbl = u @ x_proj_w^T [8192,64] K=1024, split-K=4 (BN=64)
    cudaMemsetAsync(p_xdbl, 0, (size_t)NROWS * XDBL * sizeof(float));
    {
        dim3 grid(1, NROWS / GBM, 4);
        tgemm_kernel<64, EPI_NONE, 4, false, true><<<grid, 256, GEMM_SMEM(64)>>>(
            p_xconv, D_INNER, p_wxp, nullptr, nullptr, p_xdbl, NROWS, XDBL, D_INNER);
    }

    // 7. deltaT = softplus(...), smem-transposed coalesced store (BN=64)
    {
        dim3 grid(D_INNER / 64, NROWS / GBM);
        tgemm_kernel<64, EPI_SOFTPL_T, 1, true, false><<<grid, 256, GEMM_SMEM(64)>>>(
            p_xdbl, XDBL, p_wdt, dt_proj_b, nullptr, p_dT, NROWS, D_INNER, DT_RANK);
    }

    // 8/9/10. chunked selective scan (smem B/C/z/y tiles)
    {
        dim3 grid(CS, D_INNER / 16, BATCH);
        scan_pass1<<<grid, 256>>>(A_log);
        scan_combine<<<(BATCH * D_INNER * D_STATE) / 256, 256>>>(A_log);
        scan_pass2<<<grid, 256>>>(A_log, Dv);
    }

    // 11. h_out = y @ mix_out_w^T (BN=64; rounds+permutes)
    {
        dim3 grid(DIM / 64, NROWS / GBM);
        tgemm_kernel<64, EPI_RND, 1, false, true><<<grid, 256, GEMM_SMEM(64)>>>(
            p_yscan, D_INNER, p_wmo, nullptr, nullptr, p_hout, NROWS, DIM, D_INNER);
    }

    // 12. match_pre = residual + h_out @ match_w^T + match_b (BN=64)
    {
        dim3 grid(DIM / 64, NROWS / GBM);
        tgemm_kernel<64, EPI_RESID, 1, false, false><<<grid, 256, GEMM_SMEM(64)>>>(
            p_hout, DIM, p_wma, match_b, x, p_match, NROWS, DIM, DIM);
    }

    // 13. geom_pre = h_out @ geom_w^T + geom_b (BN=64)
    {
        dim3 grid(D_GEOM / 64, NROWS / GBM);
        tgemm_kernel<64, EPI_BIAS, 1, false, false><<<grid, 256, GEMM_SMEM(64)>>>(
            p_hout, DIM, p_wge, geom_b, nullptr, p_geom, NROWS, D_GEOM, DIM);
    }

    // 14/15. final layernorms into d_out
    layernorm_kernel<false><<<NROWS, 256>>>(p_match, normm_w, normm_b, out_match, DIM);
    layernorm_kernel<false><<<NROWS, 256>>>(p_geom,  normg_w, normg_b, out_geom,  D_GEOM);
}